// round 8
// baseline (speedup 1.0000x reference)
#include <cuda_runtime.h>
#include <math.h>

// Problem constants
#define SEQ    2048
#define DMODEL 1024
#define NH     16
#define DH     64
#define BATCH  2
#define MTOT   (BATCH*SEQ)      // 4096

// Scratch (allocation-free: __device__ globals)
__device__ float g_q[BATCH*NH*SEQ*DH];   // [b,h,l,dh] 16MB
__device__ float g_k[BATCH*NH*SEQ*DH];
__device__ float g_v[BATCH*NH*SEQ*DH];
__device__ float g_y[MTOT*DMODEL];       // [b,l,d]    16MB

// ---------------------------------------------------------------------------
// Kernel 1: fused QKV projection. Classic 128x128x8 SGEMM, 256 thr, 8x8/thr.
// blockIdx.z selects {Wq,Wk,Wv}; epilogue scales q by 1/32 and writes the
// head-transposed layout [b,h,l,dh] directly.
// ---------------------------------------------------------------------------
__global__ __launch_bounds__(256) void qkv_gemm_kernel(
    const float* __restrict__ A,
    const float* __restrict__ Wq,
    const float* __restrict__ Wk,
    const float* __restrict__ Wv)
{
    const float* B; float* C; float scale;
    if (blockIdx.z == 0)      { B = Wq; C = g_q; scale = 0.03125f; }
    else if (blockIdx.z == 1) { B = Wk; C = g_k; scale = 1.0f; }
    else                      { B = Wv; C = g_v; scale = 1.0f; }

    const int tid = threadIdx.x;
    const int tx  = tid & 15;
    const int ty  = tid >> 4;
    const int m0  = blockIdx.y * 128;
    const int n0  = blockIdx.x * 128;

    __shared__ float As[8][136];   // pitch 136 keeps float4 reads 16B-aligned
    __shared__ float Bs[8][128];

    float acc[8][8];
    #pragma unroll
    for (int i = 0; i < 8; ++i)
        #pragma unroll
        for (int j = 0; j < 8; ++j) acc[i][j] = 0.0f;

    const int arow = tid >> 1;
    const int acol = (tid & 1) << 2;
    const int brow = tid >> 5;
    const int bcol = (tid & 31) << 2;

    const float* Ap = A + (size_t)(m0 + arow) * DMODEL + acol;
    const float* Bp = B + (size_t)brow * DMODEL + n0 + bcol;

    for (int kt = 0; kt < DMODEL / 8; ++kt) {
        float4 a4 = *(const float4*)Ap;
        float4 b4 = *(const float4*)Bp;
        As[acol + 0][arow] = a4.x;
        As[acol + 1][arow] = a4.y;
        As[acol + 2][arow] = a4.z;
        As[acol + 3][arow] = a4.w;
        *(float4*)&Bs[brow][bcol] = b4;
        __syncthreads();

        #pragma unroll
        for (int k = 0; k < 8; ++k) {
            float ar[8], br[8];
            *(float4*)(ar)     = *(const float4*)&As[k][(ty << 2)];
            *(float4*)(ar + 4) = *(const float4*)&As[k][64 + (ty << 2)];
            *(float4*)(br)     = *(const float4*)&Bs[k][(tx << 2)];
            *(float4*)(br + 4) = *(const float4*)&Bs[k][64 + (tx << 2)];
            #pragma unroll
            for (int i = 0; i < 8; ++i)
                #pragma unroll
                for (int j = 0; j < 8; ++j)
                    acc[i][j] += ar[i] * br[j];
        }
        __syncthreads();
        Ap += 8;
        Bp += 8 * DMODEL;
    }

    #pragma unroll
    for (int i = 0; i < 8; ++i) {
        int mi = m0 + ((i < 4) ? (ty << 2) + i : 64 + (ty << 2) + (i - 4));
        int b  = mi >> 11;
        int l  = mi & (SEQ - 1);
        #pragma unroll
        for (int j = 0; j < 8; ++j) {
            int nj = n0 + ((j < 4) ? (tx << 2) + j : 64 + (tx << 2) + (j - 4));
            int h  = nj >> 6;
            int d  = nj & 63;
            C[((size_t)((b << 4) + h) * SEQ + l) * DH + d] = acc[i][j] * scale;
        }
    }
}

// ---------------------------------------------------------------------------
// Kernel 2: RoPE in-place on g_q and g_k. Interleaved pairs (2i, 2i+1).
// inv_freq = 10000^(-2i/64) via exp2f; angle/sin/cos in fp32 to match ref.
// ---------------------------------------------------------------------------
__global__ void rope_kernel()
{
    const int half = BATCH * NH * SEQ * (DH / 2);  // 2,097,152
    int idx = blockIdx.x * blockDim.x + threadIdx.x;
    if (idx >= 2 * half) return;

    float* buf = (idx < half) ? g_q : g_k;
    int id = (idx < half) ? idx : idx - half;

    int i  = id & 31;                 // pair index 0..31
    int l  = (id >> 5) & (SEQ - 1);   // position
    int bh = id >> 16;                // (b*16+h)  since SEQ*32 = 2^16

    size_t base = ((size_t)bh * SEQ + l) * DH + (i << 1);

    // inv_freq = 2^(-2i * log2(10000)/64)
    float inv = exp2f(-(float)(2 * i) * (13.287712379549449f / 64.0f));
    float ang = (float)l * inv;
    float s, c;
    __sincosf(ang, &s, &c);
    // accurate path: use sinf/cosf for safety (tiny kernel)
    s = sinf(ang);
    c = cosf(ang);

    float x1 = buf[base];
    float x2 = buf[base + 1];
    buf[base]     = x1 * c - x2 * s;
    buf[base + 1] = x2 * c + x1 * s;
}

// ---------------------------------------------------------------------------
// Kernel 3: attention. One block = (bh, 64-query tile). Flash-style online
// softmax over 32 key tiles of 64. 256 threads, 4x4 per thread for both the
// 64x64 S tile and the 64x64 O tile. Writes O directly to [b,l,d].
// ---------------------------------------------------------------------------
#define ATTN_SMEM_FLOATS (3 * 64 * 65 + 64 * 64)
#define ATTN_SMEM_BYTES  (ATTN_SMEM_FLOATS * 4)

__global__ __launch_bounds__(256) void attn_kernel()
{
    extern __shared__ float sm[];
    float* Qs = sm;                   // [64][65]
    float* Ks = sm + 64 * 65;         // [64][65]
    float* Ps = sm + 2 * 64 * 65;     // [64][65]
    float* Vs = sm + 3 * 64 * 65;     // [64][64]

    const int tid = threadIdx.x;
    const int tx  = tid & 15;
    const int ty  = tid >> 4;
    const int ty4 = ty << 2;
    const int tx4 = tx << 2;

    const int bh = blockIdx.y;        // 0..31
    const int q0 = blockIdx.x * 64;
    const int b  = bh >> 4;
    const int h  = bh & 15;

    const float* qb    = g_q + ((size_t)bh * SEQ + q0) * DH;
    const float* kbase = g_k + (size_t)bh * SEQ * DH;
    const float* vbase = g_v + (size_t)bh * SEQ * DH;

    // Load Q tile (64x64)
    for (int idx = tid; idx < 64 * 16; idx += 256) {
        int r = idx >> 4;
        int c = (idx & 15) << 2;
        float4 v4 = *(const float4*)(qb + r * DH + c);
        Qs[r * 65 + c + 0] = v4.x;
        Qs[r * 65 + c + 1] = v4.y;
        Qs[r * 65 + c + 2] = v4.z;
        Qs[r * 65 + c + 3] = v4.w;
    }

    float mrun[4], lrun[4], o[4][4];
    #pragma unroll
    for (int i = 0; i < 4; ++i) {
        mrun[i] = -1e30f;
        lrun[i] = 0.0f;
        #pragma unroll
        for (int j = 0; j < 4; ++j) o[i][j] = 0.0f;
    }

    const int qoff = ty4 * 65;
    const int koff = tx4 * 65;

    for (int kt = 0; kt < SEQ / 64; ++kt) {
        const float* kb = kbase + (size_t)kt * 64 * DH;
        const float* vb = vbase + (size_t)kt * 64 * DH;

        __syncthreads();   // previous iteration done reading Ks/Vs/Ps (also orders Q stores on kt=0)
        for (int idx = tid; idx < 64 * 16; idx += 256) {
            int r = idx >> 4;
            int c = (idx & 15) << 2;
            float4 kv = *(const float4*)(kb + r * DH + c);
            Ks[r * 65 + c + 0] = kv.x;
            Ks[r * 65 + c + 1] = kv.y;
            Ks[r * 65 + c + 2] = kv.z;
            Ks[r * 65 + c + 3] = kv.w;
            float4 vv = *(const float4*)(vb + r * DH + c);
            *(float4*)&Vs[r * 64 + c] = vv;
        }
        __syncthreads();

        // S = Q K^T  (4x4 per thread)
        float s[4][4];
        #pragma unroll
        for (int i = 0; i < 4; ++i)
            #pragma unroll
            for (int j = 0; j < 4; ++j) s[i][j] = 0.0f;

        #pragma unroll 8
        for (int k = 0; k < 64; ++k) {
            float a0 = Qs[qoff + 0 * 65 + k];
            float a1 = Qs[qoff + 1 * 65 + k];
            float a2 = Qs[qoff + 2 * 65 + k];
            float a3 = Qs[qoff + 3 * 65 + k];
            float b0 = Ks[koff + 0 * 65 + k];
            float b1 = Ks[koff + 1 * 65 + k];
            float b2 = Ks[koff + 2 * 65 + k];
            float b3 = Ks[koff + 3 * 65 + k];
            s[0][0] += a0 * b0; s[0][1] += a0 * b1; s[0][2] += a0 * b2; s[0][3] += a0 * b3;
            s[1][0] += a1 * b0; s[1][1] += a1 * b1; s[1][2] += a1 * b2; s[1][3] += a1 * b3;
            s[2][0] += a2 * b0; s[2][1] += a2 * b1; s[2][2] += a2 * b2; s[2][3] += a2 * b3;
            s[3][0] += a3 * b0; s[3][1] += a3 * b1; s[3][2] += a3 * b2; s[3][3] += a3 * b3;
        }

        // Online softmax per row (rows ty4..ty4+3; reduce across tx = lane bits 0..3)
        #pragma unroll
        for (int i = 0; i < 4; ++i) {
            float tm = fmaxf(fmaxf(s[i][0], s[i][1]), fmaxf(s[i][2], s[i][3]));
            #pragma unroll
            for (int off = 8; off >= 1; off >>= 1)
                tm = fmaxf(tm, __shfl_xor_sync(0xffffffffu, tm, off));
            float mnew  = fmaxf(mrun[i], tm);
            float alpha = __expf(mrun[i] - mnew);
            mrun[i] = mnew;
            float rs = 0.0f;
            #pragma unroll
            for (int j = 0; j < 4; ++j) {
                float p = __expf(s[i][j] - mnew);
                s[i][j] = p;
                rs += p;
            }
            #pragma unroll
            for (int off = 8; off >= 1; off >>= 1)
                rs += __shfl_xor_sync(0xffffffffu, rs, off);
            lrun[i] = lrun[i] * alpha + rs;
            #pragma unroll
            for (int j = 0; j < 4; ++j) o[i][j] *= alpha;
        }

        // Stage P
        #pragma unroll
        for (int i = 0; i < 4; ++i)
            #pragma unroll
            for (int j = 0; j < 4; ++j)
                Ps[(ty4 + i) * 65 + tx4 + j] = s[i][j];
        __syncthreads();

        // O += P V  (4 rows x 4 dh-cols per thread)
        #pragma unroll 8
        for (int k = 0; k < 64; ++k) {
            float p0 = Ps[qoff + 0 * 65 + k];
            float p1 = Ps[qoff + 1 * 65 + k];
            float p2 = Ps[qoff + 2 * 65 + k];
            float p3 = Ps[qoff + 3 * 65 + k];
            float4 vv = *(const float4*)&Vs[k * 64 + tx4];
            o[0][0] += p0 * vv.x; o[0][1] += p0 * vv.y; o[0][2] += p0 * vv.z; o[0][3] += p0 * vv.w;
            o[1][0] += p1 * vv.x; o[1][1] += p1 * vv.y; o[1][2] += p1 * vv.z; o[1][3] += p1 * vv.w;
            o[2][0] += p2 * vv.x; o[2][1] += p2 * vv.y; o[2][2] += p2 * vv.z; o[2][3] += p2 * vv.w;
            o[3][0] += p3 * vv.x; o[3][1] += p3 * vv.y; o[3][2] += p3 * vv.z; o[3][3] += p3 * vv.w;
        }
    }

    // Epilogue: normalize and write [b,l,d]
    #pragma unroll
    for (int i = 0; i < 4; ++i) {
        float inv = 1.0f / lrun[i];
        int l = q0 + ty4 + i;
        float* yrow = g_y + ((size_t)b * SEQ + l) * DMODEL + h * DH + tx4;
        yrow[0] = o[i][0] * inv;
        yrow[1] = o[i][1] * inv;
        yrow[2] = o[i][2] * inv;
        yrow[3] = o[i][3] * inv;
    }
}

// ---------------------------------------------------------------------------
// Kernel 4: output projection  d_out = g_y @ Wo   (plain 128x128x8 SGEMM)
// ---------------------------------------------------------------------------
__global__ __launch_bounds__(256) void oproj_kernel(
    const float* __restrict__ B, float* __restrict__ C)
{
    const float* A = g_y;

    const int tid = threadIdx.x;
    const int tx  = tid & 15;
    const int ty  = tid >> 4;
    const int m0  = blockIdx.y * 128;
    const int n0  = blockIdx.x * 128;

    __shared__ float As[8][136];
    __shared__ float Bs[8][128];

    float acc[8][8];
    #pragma unroll
    for (int i = 0; i < 8; ++i)
        #pragma unroll
        for (int j = 0; j < 8; ++j) acc[i][j] = 0.0f;

    const int arow = tid >> 1;
    const int acol = (tid & 1) << 2;
    const int brow = tid >> 5;
    const int bcol = (tid & 31) << 2;

    const float* Ap = A + (size_t)(m0 + arow) * DMODEL + acol;
    const float* Bp = B + (size_t)brow * DMODEL + n0 + bcol;

    for (int kt = 0; kt < DMODEL / 8; ++kt) {
        float4 a4 = *(const float4*)Ap;
        float4 b4 = *(const float4*)Bp;
        As[acol + 0][arow] = a4.x;
        As[acol + 1][arow] = a4.y;
        As[acol + 2][arow] = a4.z;
        As[acol + 3][arow] = a4.w;
        *(float4*)&Bs[brow][bcol] = b4;
        __syncthreads();

        #pragma unroll
        for (int k = 0; k < 8; ++k) {
            float ar[8], br[8];
            *(float4*)(ar)     = *(const float4*)&As[k][(ty << 2)];
            *(float4*)(ar + 4) = *(const float4*)&As[k][64 + (ty << 2)];
            *(float4*)(br)     = *(const float4*)&Bs[k][(tx << 2)];
            *(float4*)(br + 4) = *(const float4*)&Bs[k][64 + (tx << 2)];
            #pragma unroll
            for (int i = 0; i < 8; ++i)
                #pragma unroll
                for (int j = 0; j < 8; ++j)
                    acc[i][j] += ar[i] * br[j];
        }
        __syncthreads();
        Ap += 8;
        Bp += 8 * DMODEL;
    }

    #pragma unroll
    for (int i = 0; i < 8; ++i) {
        int mi = m0 + ((i < 4) ? (ty << 2) + i : 64 + (ty << 2) + (i - 4));
        #pragma unroll
        for (int j = 0; j < 8; ++j) {
            int nj = n0 + ((j < 4) ? (tx << 2) + j : 64 + (tx << 2) + (j - 4));
            C[(size_t)mi * DMODEL + nj] = acc[i][j];
        }
    }
}

// ---------------------------------------------------------------------------
extern "C" void kernel_launch(void* const* d_in, const int* in_sizes, int n_in,
                              void* d_out, int out_size)
{
    (void)in_sizes; (void)n_in; (void)out_size;
    const float* x  = (const float*)d_in[0];
    const float* Wq = (const float*)d_in[1];
    const float* Wk = (const float*)d_in[2];
    const float* Wv = (const float*)d_in[3];
    const float* Wo = (const float*)d_in[4];
    float* out = (float*)d_out;

    // Idempotent, deterministic, not a stream op — safe during graph capture.
    cudaFuncSetAttribute(attn_kernel,
                         cudaFuncAttributeMaxDynamicSharedMemorySize,
                         ATTN_SMEM_BYTES);

    qkv_gemm_kernel<<<dim3(DMODEL / 128, MTOT / 128, 3), 256>>>(x, Wq, Wk, Wv);

    {
        int total  = 2 * BATCH * NH * SEQ * (DH / 2);
        int blocks = (total + 255) / 256;
        rope_kernel<<<blocks, 256>>>();
    }

    attn_kernel<<<dim3(SEQ / 64, BATCH * NH), 256, ATTN_SMEM_BYTES>>>();

    oproj_kernel<<<dim3(DMODEL / 128, MTOT / 128), 256>>>(Wo, out);
}

// round 9
// speedup vs baseline: 2.9195x; 2.9195x over previous
#include <cuda_runtime.h>
#include <math.h>

// Problem constants
#define SEQ    2048
#define DMODEL 1024
#define NH     16
#define DH     64
#define BATCH  2
#define MTOT   (BATCH*SEQ)      // 4096

// Scratch (allocation-free: __device__ globals)
__device__ float g_q[BATCH*NH*SEQ*DH];   // [b,h,l,dh]
__device__ float g_k[BATCH*NH*SEQ*DH];
__device__ float g_v[BATCH*NH*SEQ*DH];
__device__ float g_y[MTOT*DMODEL];       // [b,l,d]

// ---------------------------------------------------------------------------
// tf32 helpers
// ---------------------------------------------------------------------------
__device__ __forceinline__ float tfr(float x) {
    unsigned u;
    asm("cvt.rna.tf32.f32 %0, %1;" : "=r"(u) : "f"(x));
    return __uint_as_float(u);
}
__device__ __forceinline__ float4 tfr4(float4 a) {
    a.x = tfr(a.x); a.y = tfr(a.y); a.z = tfr(a.z); a.w = tfr(a.w);
    return a;
}
__device__ __forceinline__ void mma_tf32(float c[4],
                                         unsigned a0, unsigned a1, unsigned a2, unsigned a3,
                                         unsigned b0, unsigned b1) {
    asm volatile(
        "mma.sync.aligned.m16n8k8.row.col.f32.tf32.tf32.f32 "
        "{%0,%1,%2,%3}, {%4,%5,%6,%7}, {%8,%9}, {%0,%1,%2,%3};\n"
        : "+f"(c[0]), "+f"(c[1]), "+f"(c[2]), "+f"(c[3])
        : "r"(a0), "r"(a1), "r"(a2), "r"(a3), "r"(b0), "r"(b1));
}

// ---------------------------------------------------------------------------
// Shared GEMM body: C[128x128 tile] = A[M,1024] @ B[1024,N tile] (tf32 mma).
// 256 threads = 8 warps (2x4 m/n), warp tile 64x32, K-tile 16.
// Register-prefetch + double-buffered smem, one __syncthreads per K-tile.
// Pitches: A=20 (lane bank (t/4)*4+t%4, conflict-free), B=136 ((t%4)*8+t/4).
// ---------------------------------------------------------------------------
#define APITCH 20
#define BPITCH 136

__device__ __forceinline__ void gemm128_tf32(const float* __restrict__ A,
                                             const float* __restrict__ B,
                                             float* __restrict__ C,
                                             float scale, bool qkv_layout)
{
    __shared__ float As[2][128 * APITCH];
    __shared__ float Bs[2][16 * BPITCH];

    const int tid  = threadIdx.x;
    const int lane = tid & 31;
    const int w    = tid >> 5;
    const int g    = lane >> 2;
    const int tg   = lane & 3;
    const int wm   = (w & 1) * 64;
    const int wn   = (w >> 1) * 32;
    const int m0   = blockIdx.y * 128;
    const int n0   = blockIdx.x * 128;

    // gmem load slots: A tile 128x16 (512 float4, 2/thread), B tile 16x128
    const int ar0 = tid >> 2;
    const int ac  = (tid & 3) << 2;
    const int br0 = tid >> 5;
    const int bc  = (tid & 31) << 2;

    float c[4][4][4];
    #pragma unroll
    for (int i = 0; i < 4; ++i)
        #pragma unroll
        for (int j = 0; j < 4; ++j)
            #pragma unroll
            for (int v = 0; v < 4; ++v) c[i][j][v] = 0.0f;

    float4 aR0, aR1, bR0, bR1;

    // prologue: K-tile 0 -> buffer 0
    aR0 = *(const float4*)(A + (size_t)(m0 + ar0) * DMODEL + ac);
    aR1 = *(const float4*)(A + (size_t)(m0 + 64 + ar0) * DMODEL + ac);
    bR0 = *(const float4*)(B + (size_t)br0 * DMODEL + n0 + bc);
    bR1 = *(const float4*)(B + (size_t)(8 + br0) * DMODEL + n0 + bc);
    *(float4*)&As[0][ar0 * APITCH + ac]        = tfr4(aR0);
    *(float4*)&As[0][(64 + ar0) * APITCH + ac] = tfr4(aR1);
    *(float4*)&Bs[0][br0 * BPITCH + bc]        = tfr4(bR0);
    *(float4*)&Bs[0][(8 + br0) * BPITCH + bc]  = tfr4(bR1);
    __syncthreads();

    for (int kt = 0; kt < 64; ++kt) {
        const int buf = kt & 1;
        if (kt < 63) {
            const float* Ap = A + (size_t)m0 * DMODEL + (kt + 1) * 16;
            const float* Bp = B + (size_t)((kt + 1) * 16) * DMODEL + n0;
            aR0 = *(const float4*)(Ap + (size_t)ar0 * DMODEL + ac);
            aR1 = *(const float4*)(Ap + (size_t)(64 + ar0) * DMODEL + ac);
            bR0 = *(const float4*)(Bp + (size_t)br0 * DMODEL + bc);
            bR1 = *(const float4*)(Bp + (size_t)(8 + br0) * DMODEL + bc);
        }

        #pragma unroll
        for (int kk = 0; kk < 2; ++kk) {
            unsigned af[4][4], bf[4][2];
            #pragma unroll
            for (int i = 0; i < 4; ++i) {
                const int r = wm + i * 16 + g;
                af[i][0] = __float_as_uint(As[buf][r * APITCH + kk * 8 + tg]);
                af[i][1] = __float_as_uint(As[buf][(r + 8) * APITCH + kk * 8 + tg]);
                af[i][2] = __float_as_uint(As[buf][r * APITCH + kk * 8 + tg + 4]);
                af[i][3] = __float_as_uint(As[buf][(r + 8) * APITCH + kk * 8 + tg + 4]);
            }
            #pragma unroll
            for (int j = 0; j < 4; ++j) {
                const int nn = wn + j * 8 + g;
                bf[j][0] = __float_as_uint(Bs[buf][(kk * 8 + tg) * BPITCH + nn]);
                bf[j][1] = __float_as_uint(Bs[buf][(kk * 8 + tg + 4) * BPITCH + nn]);
            }
            #pragma unroll
            for (int i = 0; i < 4; ++i)
                #pragma unroll
                for (int j = 0; j < 4; ++j)
                    mma_tf32(c[i][j], af[i][0], af[i][1], af[i][2], af[i][3],
                             bf[j][0], bf[j][1]);
        }

        if (kt < 63) {
            *(float4*)&As[buf ^ 1][ar0 * APITCH + ac]        = tfr4(aR0);
            *(float4*)&As[buf ^ 1][(64 + ar0) * APITCH + ac] = tfr4(aR1);
            *(float4*)&Bs[buf ^ 1][br0 * BPITCH + bc]        = tfr4(bR0);
            *(float4*)&Bs[buf ^ 1][(8 + br0) * BPITCH + bc]  = tfr4(bR1);
        }
        __syncthreads();
    }

    // epilogue
    #pragma unroll
    for (int i = 0; i < 4; ++i) {
        const int mrow0 = m0 + wm + i * 16 + g;
        const int mrow1 = mrow0 + 8;
        #pragma unroll
        for (int j = 0; j < 4; ++j) {
            const int ncol = n0 + wn + j * 8 + 2 * tg;
            if (qkv_layout) {
                const int h_ = ncol >> 6, d_ = ncol & 63;
                {
                    const int b_ = mrow0 >> 11, l_ = mrow0 & (SEQ - 1);
                    float* p = C + (((size_t)(b_ * NH + h_) * SEQ + l_) * DH + d_);
                    p[0] = c[i][j][0] * scale;
                    p[1] = c[i][j][1] * scale;
                }
                {
                    const int b_ = mrow1 >> 11, l_ = mrow1 & (SEQ - 1);
                    float* p = C + (((size_t)(b_ * NH + h_) * SEQ + l_) * DH + d_);
                    p[0] = c[i][j][2] * scale;
                    p[1] = c[i][j][3] * scale;
                }
            } else {
                float* p0 = C + (size_t)mrow0 * DMODEL + ncol;
                p0[0] = c[i][j][0]; p0[1] = c[i][j][1];
                float* p1 = C + (size_t)mrow1 * DMODEL + ncol;
                p1[0] = c[i][j][2]; p1[1] = c[i][j][3];
            }
        }
    }
}

// ---------------------------------------------------------------------------
// Kernel 1: fused QKV projection (blockIdx.z picks W; q scaled by 1/32)
// ---------------------------------------------------------------------------
__global__ __launch_bounds__(256) void qkv_mma_kernel(
    const float* __restrict__ A,
    const float* __restrict__ Wq,
    const float* __restrict__ Wk,
    const float* __restrict__ Wv)
{
    const float* B; float* C; float scale;
    if (blockIdx.z == 0)      { B = Wq; C = g_q; scale = 0.03125f; }
    else if (blockIdx.z == 1) { B = Wk; C = g_k; scale = 1.0f; }
    else                      { B = Wv; C = g_v; scale = 1.0f; }
    gemm128_tf32(A, B, C, scale, true);
}

// ---------------------------------------------------------------------------
// Kernel 4: output projection  d_out = g_y @ Wo
// ---------------------------------------------------------------------------
__global__ __launch_bounds__(256) void oproj_mma_kernel(
    const float* __restrict__ Wo, float* __restrict__ C)
{
    gemm128_tf32(g_y, Wo, C, 1.0f, false);
}

// ---------------------------------------------------------------------------
// Kernel 2: RoPE in-place on g_q and g_k (fp32, interleaved pairs).
// ---------------------------------------------------------------------------
__global__ void rope_kernel()
{
    const int half = BATCH * NH * SEQ * (DH / 2);
    int idx = blockIdx.x * blockDim.x + threadIdx.x;
    if (idx >= 2 * half) return;

    float* buf = (idx < half) ? g_q : g_k;
    int id = (idx < half) ? idx : idx - half;

    int i  = id & 31;
    int l  = (id >> 5) & (SEQ - 1);
    int bh = id >> 16;

    size_t base = ((size_t)bh * SEQ + l) * DH + (i << 1);

    float inv = exp2f(-(float)(2 * i) * (13.287712379549449f / 64.0f));
    float ang = (float)l * inv;
    float s = sinf(ang);
    float c = cosf(ang);

    float x1 = buf[base];
    float x2 = buf[base + 1];
    buf[base]     = x1 * c - x2 * s;
    buf[base + 1] = x2 * c + x1 * s;
}

// ---------------------------------------------------------------------------
// Kernel 3: flash attention, tensor cores. One block = (bh, 64 q-rows).
// 4 warps of 32; warp w owns q rows [w*16, w*16+16). Q fragments live in
// registers across all 32 key tiles. K/V/P staged in smem with conflict-free
// pitches (68, 72, 68). P is warp-private -> __syncwarp only.
// ---------------------------------------------------------------------------
#define QP 68
#define VP 72
#define ATTN_SM_FLOATS (64*QP + 64*VP + 64*QP)
#define ATTN_SM_BYTES  (ATTN_SM_FLOATS * 4)

__global__ __launch_bounds__(128) void attn_mma_kernel()
{
    extern __shared__ float sm[];
    float* Ks = sm;                       // [64][68] (also Q staging)
    float* Vs = sm + 64 * QP;             // [64][72]
    float* Ps = sm + 64 * QP + 64 * VP;   // [64][68]

    const int tid  = threadIdx.x;
    const int lane = tid & 31;
    const int w    = tid >> 5;
    const int g    = lane >> 2;
    const int tg   = lane & 3;

    const int bh = blockIdx.y;
    const int q0 = blockIdx.x * 64;
    const int b  = bh >> 4;
    const int h  = bh & 15;

    const float* qb    = g_q + ((size_t)bh * SEQ + q0) * DH;
    const float* kbase = g_k + (size_t)bh * SEQ * DH;
    const float* vbase = g_v + (size_t)bh * SEQ * DH;

    // stage Q (tf32-rounded) and pull fragments into registers
    #pragma unroll
    for (int it = 0; it < 8; ++it) {
        const int idx = it * 128 + tid;
        const int r = idx >> 4, cc = (idx & 15) << 2;
        *(float4*)&Ks[r * QP + cc] = tfr4(*(const float4*)(qb + r * DH + cc));
    }
    __syncthreads();

    unsigned qa[8][4];
    {
        const int r = w * 16 + g;
        #pragma unroll
        for (int kk = 0; kk < 8; ++kk) {
            qa[kk][0] = __float_as_uint(Ks[r * QP + kk * 8 + tg]);
            qa[kk][1] = __float_as_uint(Ks[(r + 8) * QP + kk * 8 + tg]);
            qa[kk][2] = __float_as_uint(Ks[r * QP + kk * 8 + tg + 4]);
            qa[kk][3] = __float_as_uint(Ks[(r + 8) * QP + kk * 8 + tg + 4]);
        }
    }
    __syncthreads();   // done with Q staging buffer before K overwrites it

    float mr0 = -1e30f, mr1 = -1e30f, lr0 = 0.0f, lr1 = 0.0f;
    float o[8][4];
    #pragma unroll
    for (int j = 0; j < 8; ++j)
        #pragma unroll
        for (int v = 0; v < 4; ++v) o[j][v] = 0.0f;

    const int pr = w * 16 + g;   // this thread's base P/Q row

    for (int kt = 0; kt < 32; ++kt) {
        const float* kb = kbase + (size_t)kt * 64 * DH;
        const float* vb = vbase + (size_t)kt * 64 * DH;
        #pragma unroll
        for (int it = 0; it < 8; ++it) {
            const int idx = it * 128 + tid;
            const int r = idx >> 4, cc = (idx & 15) << 2;
            *(float4*)&Ks[r * QP + cc] = tfr4(*(const float4*)(kb + r * DH + cc));
            *(float4*)&Vs[r * VP + cc] = tfr4(*(const float4*)(vb + r * DH + cc));
        }
        __syncthreads();

        // S = Q K^T : warp computes 16x64 in 8 n-tiles
        float s[8][4];
        #pragma unroll
        for (int j = 0; j < 8; ++j)
            #pragma unroll
            for (int v = 0; v < 4; ++v) s[j][v] = 0.0f;

        #pragma unroll
        for (int kk = 0; kk < 8; ++kk) {
            #pragma unroll
            for (int j = 0; j < 8; ++j) {
                const unsigned b0 = __float_as_uint(Ks[(j * 8 + g) * QP + kk * 8 + tg]);
                const unsigned b1 = __float_as_uint(Ks[(j * 8 + g) * QP + kk * 8 + tg + 4]);
                mma_tf32(s[j], qa[kk][0], qa[kk][1], qa[kk][2], qa[kk][3], b0, b1);
            }
        }

        // online softmax for rows pr (c0,c1) and pr+8 (c2,c3)
        float tm0 = -1e30f, tm1 = -1e30f;
        #pragma unroll
        for (int j = 0; j < 8; ++j) {
            tm0 = fmaxf(tm0, fmaxf(s[j][0], s[j][1]));
            tm1 = fmaxf(tm1, fmaxf(s[j][2], s[j][3]));
        }
        tm0 = fmaxf(tm0, __shfl_xor_sync(0xffffffffu, tm0, 1));
        tm0 = fmaxf(tm0, __shfl_xor_sync(0xffffffffu, tm0, 2));
        tm1 = fmaxf(tm1, __shfl_xor_sync(0xffffffffu, tm1, 1));
        tm1 = fmaxf(tm1, __shfl_xor_sync(0xffffffffu, tm1, 2));

        const float mn0 = fmaxf(mr0, tm0);
        const float mn1 = fmaxf(mr1, tm1);
        const float a0  = __expf(mr0 - mn0);
        const float a1  = __expf(mr1 - mn1);
        mr0 = mn0; mr1 = mn1;

        float rs0 = 0.0f, rs1 = 0.0f;
        #pragma unroll
        for (int j = 0; j < 8; ++j) {
            s[j][0] = __expf(s[j][0] - mn0);
            s[j][1] = __expf(s[j][1] - mn0);
            s[j][2] = __expf(s[j][2] - mn1);
            s[j][3] = __expf(s[j][3] - mn1);
            rs0 += s[j][0] + s[j][1];
            rs1 += s[j][2] + s[j][3];
        }
        rs0 += __shfl_xor_sync(0xffffffffu, rs0, 1);
        rs0 += __shfl_xor_sync(0xffffffffu, rs0, 2);
        rs1 += __shfl_xor_sync(0xffffffffu, rs1, 1);
        rs1 += __shfl_xor_sync(0xffffffffu, rs1, 2);
        lr0 = lr0 * a0 + rs0;
        lr1 = lr1 * a1 + rs1;

        #pragma unroll
        for (int j = 0; j < 8; ++j) {
            o[j][0] *= a0; o[j][1] *= a0;
            o[j][2] *= a1; o[j][3] *= a1;
        }

        // stage P (tf32) — warp-private rows, so warp-level sync is enough
        #pragma unroll
        for (int j = 0; j < 8; ++j) {
            *(float2*)&Ps[pr * QP + j * 8 + 2 * tg] =
                make_float2(tfr(s[j][0]), tfr(s[j][1]));
            *(float2*)&Ps[(pr + 8) * QP + j * 8 + 2 * tg] =
                make_float2(tfr(s[j][2]), tfr(s[j][3]));
        }
        __syncwarp();

        // O += P V
        #pragma unroll
        for (int kk = 0; kk < 8; ++kk) {
            const unsigned p0 = __float_as_uint(Ps[pr * QP + kk * 8 + tg]);
            const unsigned p1 = __float_as_uint(Ps[(pr + 8) * QP + kk * 8 + tg]);
            const unsigned p2 = __float_as_uint(Ps[pr * QP + kk * 8 + tg + 4]);
            const unsigned p3 = __float_as_uint(Ps[(pr + 8) * QP + kk * 8 + tg + 4]);
            #pragma unroll
            for (int j = 0; j < 8; ++j) {
                const unsigned vb0 = __float_as_uint(Vs[(kk * 8 + tg) * VP + j * 8 + g]);
                const unsigned vb1 = __float_as_uint(Vs[(kk * 8 + tg + 4) * VP + j * 8 + g]);
                mma_tf32(o[j], p0, p1, p2, p3, vb0, vb1);
            }
        }
        __syncthreads();   // all warps done with Ks/Vs before next tile load
    }

    // epilogue: normalize, write [b,l,d]
    const float i0 = 1.0f / lr0;
    const float i1 = 1.0f / lr1;
    const int l0 = q0 + pr;
    const int l1 = l0 + 8;
    #pragma unroll
    for (int j = 0; j < 8; ++j) {
        const int col = h * DH + j * 8 + 2 * tg;
        *(float2*)&g_y[((size_t)b * SEQ + l0) * DMODEL + col] =
            make_float2(o[j][0] * i0, o[j][1] * i0);
        *(float2*)&g_y[((size_t)b * SEQ + l1) * DMODEL + col] =
            make_float2(o[j][2] * i1, o[j][3] * i1);
    }
}

// ---------------------------------------------------------------------------
extern "C" void kernel_launch(void* const* d_in, const int* in_sizes, int n_in,
                              void* d_out, int out_size)
{
    (void)in_sizes; (void)n_in; (void)out_size;
    const float* x  = (const float*)d_in[0];
    const float* Wq = (const float*)d_in[1];
    const float* Wk = (const float*)d_in[2];
    const float* Wv = (const float*)d_in[3];
    const float* Wo = (const float*)d_in[4];
    float* out = (float*)d_out;

    // Idempotent attribute set; not a stream op — safe under graph capture.
    cudaFuncSetAttribute(attn_mma_kernel,
                         cudaFuncAttributeMaxDynamicSharedMemorySize,
                         ATTN_SM_BYTES);

    qkv_mma_kernel<<<dim3(DMODEL / 128, MTOT / 128, 3), 256>>>(x, Wq, Wk, Wv);

    {
        int total  = 2 * BATCH * NH * SEQ * (DH / 2);
        int blocks = (total + 255) / 256;
        rope_kernel<<<blocks, 256>>>();
    }

    attn_mma_kernel<<<dim3(SEQ / 64, BATCH * NH), 128, ATTN_SM_BYTES>>>();

    oproj_mma_kernel<<<dim3(DMODEL / 128, MTOT / 128), 256>>>(Wo, out);
}